// round 13
// baseline (speedup 1.0000x reference)
#include <cuda_runtime.h>
#include <cuda_fp16.h>
#include <math.h>
#include <stdint.h>

// Problem constants (fixed by the reference)
#define B_   16
#define NQ_  2048
#define NK_  2048
#define D_   128

// Tiling
#define BM       128     // queries per block
#define BN       64      // keys per tile
#define NT       32      // NK_/BN tiles
#define NTHREADS 512     // 16 warps

// smem pitches in halves — word-pitch ≡ 4 (mod 32) -> conflict-free ldmatrix
#define QPH 136
#define KPH 136
#define VPH 136
#define EPH 72

// smem byte layout (all 16B aligned)
#define QS_OFF   0
#define QS_BYTES (BM * QPH * 2)                 // 34816
#define KS_OFF   (QS_OFF + QS_BYTES)
#define KS_BYTES (BN * KPH * 2)                 // 17408 per buffer
#define VS_OFF   (KS_OFF + 2 * KS_BYTES)
#define VS_BYTES (BN * VPH * 2)                 // 17408 per buffer
#define ES_OFF   (VS_OFF + 2 * VS_BYTES)
#define ES_BYTES (BM * EPH * 2)                 // 18432
#define LS_OFF   (ES_OFF + ES_BYTES)
#define SMEM_BYTES (LS_OFF + 4 * BM * 4)        // 124928

__device__ float  g_gate[NK_];                     // gate * 1/sqrt(d)
__device__ __half g_Kh[(size_t)B_ * NK_ * D_];     // K * gate * scale, fp16
__device__ __half g_Vh[(size_t)B_ * NK_ * D_];     // V, fp16 (row-major [key][d])

// ---------------------------------------------------------------------------
__global__ void gate_kernel(const float* __restrict__ phases) {
    int k = blockIdx.x * blockDim.x + threadIdx.x;
    if (k < NK_) {
        const float TWO_PI = 6.283185307179586f;
        const float INV_2PW2 = 1.0f / 1.2337005501361697f; // 2*(2pi/8)^2
        const float SCALE = 0.08838834764831845f;          // 1/sqrt(128)
        float p = fabsf(phases[k]);
        float pd = fminf(p, TWO_PI - p);
        g_gate[k] = expf(-pd * pd * INV_2PW2) * SCALE;
    }
}

// K -> fp16 with gate*scale folded; V -> fp16 plain. One thread per 4 elems.
__global__ void convK_kernel(const float* __restrict__ K) {
    int i = blockIdx.x * blockDim.x + threadIdx.x;   // < B*NK*D/4 = 2^20
    int d4  = (i & 31) << 2;
    int row = i >> 5;
    float gs = g_gate[row & (NK_ - 1)];
    float4 v = *(const float4*)(K + (size_t)row * D_ + d4);
    __half2 h0 = __floats2half2_rn(v.x * gs, v.y * gs);
    __half2 h1 = __floats2half2_rn(v.z * gs, v.w * gs);
    uint2 u = make_uint2(*(uint32_t*)&h0, *(uint32_t*)&h1);
    *(uint2*)&g_Kh[(size_t)row * D_ + d4] = u;
}

__global__ void convV_kernel(const float* __restrict__ V) {
    int i = blockIdx.x * blockDim.x + threadIdx.x;   // < 2^20
    int d4  = (i & 31) << 2;
    int row = i >> 5;
    float4 v = *(const float4*)(V + (size_t)row * D_ + d4);
    __half2 h0 = __floats2half2_rn(v.x, v.y);
    __half2 h1 = __floats2half2_rn(v.z, v.w);
    uint2 u = make_uint2(*(uint32_t*)&h0, *(uint32_t*)&h1);
    *(uint2*)&g_Vh[(size_t)row * D_ + d4] = u;
}

// ---------------------------------------------------------------------------
__device__ __forceinline__ void mma_f16(
    float& d0, float& d1, float& d2, float& d3,
    uint32_t a0, uint32_t a1, uint32_t a2, uint32_t a3,
    uint32_t b0, uint32_t b1)
{
    asm volatile(
        "mma.sync.aligned.m16n8k16.row.col.f32.f16.f16.f32 "
        "{%0,%1,%2,%3}, {%4,%5,%6,%7}, {%8,%9}, {%0,%1,%2,%3};"
        : "+f"(d0), "+f"(d1), "+f"(d2), "+f"(d3)
        : "r"(a0), "r"(a1), "r"(a2), "r"(a3), "r"(b0), "r"(b1));
}

__device__ __forceinline__ void ldsm_x4(uint32_t* r, uint32_t addr) {
    asm volatile("ldmatrix.sync.aligned.m8n8.x4.shared.b16 {%0,%1,%2,%3}, [%4];"
                 : "=r"(r[0]), "=r"(r[1]), "=r"(r[2]), "=r"(r[3]) : "r"(addr));
}

__device__ __forceinline__ void ldsm_x4_trans(uint32_t* r, uint32_t addr) {
    asm volatile("ldmatrix.sync.aligned.m8n8.x4.trans.shared.b16 {%0,%1,%2,%3}, [%4];"
                 : "=r"(r[0]), "=r"(r[1]), "=r"(r[2]), "=r"(r[3]) : "r"(addr));
}

__device__ __forceinline__ void cp16(uint32_t dst, const void* src) {
    asm volatile("cp.async.ca.shared.global [%0], [%1], 16;"
                 :: "r"(dst), "l"(src));
}

// ---------------------------------------------------------------------------
// Fused attention: fp16 mma, ldmatrix fragments, cp.async double-buffered K/V,
// in-kernel attn rescale tail (each CTA owns its 128 rows end-to-end).
// Single pass over K: E = exp(score) written UNNORMALIZED to attn; row-sum l
// and O = sum(E*v) accumulated; O and attn normalized at the end.
// (No max subtraction: |score| <= ~6 here, mathematically exact.)
// ---------------------------------------------------------------------------
extern __shared__ char smem[];

__global__ void __launch_bounds__(NTHREADS, 1)
attn_kernel(const float* __restrict__ Q, float* __restrict__ out,
            float* __restrict__ attn)
{
    uint32_t sb = (uint32_t)__cvta_generic_to_shared(smem);
    uint32_t* Qsw = (uint32_t*)(smem + QS_OFF);
    uint32_t* Esw = (uint32_t*)(smem + ES_OFF);
    float*    lsm = (float*)(smem + LS_OFF);     // [4][BM] partials -> [BM] inv

    const int b    = blockIdx.y;
    const int q0   = blockIdx.x * BM;
    const int brow = b * NQ_ + q0;

    const int tid  = threadIdx.x;
    const int lane = tid & 31;
    const int wid  = tid >> 5;
    const int g    = lane >> 2;        // 0..7
    const int t    = lane & 3;         // 0..3
    const int wm   = wid >> 2;         // 0..3 -> 32-row slab
    const int wn   = wid & 3;          // 0..3 -> 16-col (S) / 32-col (PV) slab

    // ldmatrix per-lane source-row decomposition
    const int mi = lane >> 3;          // matrix index 0..3
    const int rr = lane & 7;           // row within matrix

    // ---- stage Q [BM][D] fp32 -> fp16 smem ----
    const float* Qg = Q + (size_t)brow * D_;
    for (int i = tid; i < BM * (D_ / 4); i += NTHREADS) {
        int m  = i >> 5;
        int d4 = (i & 31) << 2;
        float4 v = *(const float4*)(Qg + m * D_ + d4);
        __half2 h0 = __floats2half2_rn(v.x, v.y);
        __half2 h1 = __floats2half2_rn(v.z, v.w);
        uint2 u = make_uint2(*(uint32_t*)&h0, *(uint32_t*)&h1);
        *(uint2*)&Qsw[(m * QPH + d4) >> 1] = u;
    }

    // tile staging via cp.async (16B chunks; 2+2 per thread per tile)
    const __half* KhB = g_Kh + (size_t)b * NK_ * D_;
    const __half* VhB = g_Vh + (size_t)b * NK_ * D_;
    auto stage = [&](int buf, int kt) {
        const int k0 = kt * BN;
        uint32_t kdst = sb + KS_OFF + buf * KS_BYTES;
        uint32_t vdst = sb + VS_OFF + buf * VS_BYTES;
        const __half* ksrc = KhB + (size_t)k0 * D_;
        const __half* vsrc = VhB + (size_t)k0 * D_;
        #pragma unroll
        for (int r = 0; r < 2; r++) {
            int i = tid + r * NTHREADS;          // < 1024
            int row = i >> 4, off = i & 15;
            cp16(kdst + row * (KPH * 2) + off * 16, ksrc + row * D_ + off * 8);
            cp16(vdst + row * (VPH * 2) + off * 16, vsrc + row * D_ + off * 8);
        }
        asm volatile("cp.async.commit_group;");
    };

    stage(0, 0);

    float oacc[2][4][4];
    #pragma unroll
    for (int i = 0; i < 2; i++)
        #pragma unroll
        for (int j = 0; j < 4; j++)
            #pragma unroll
            for (int r = 0; r < 4; r++) oacc[i][j][r] = 0.0f;
    float lsum[2][2] = {{0.0f, 0.0f}, {0.0f, 0.0f}};

    // lane-constant ldmatrix address bases (halves -> bytes at use)
    const int arow  = wm * 32 + rr + (mi & 1) * 8;          // + i*16
    const int acolh = (mi >> 1) * 8;
    const uint32_t qaddr0 = sb + QS_OFF + (uint32_t)(arow * QPH + acolh) * 2;
    const uint32_t eaddr0 = sb + ES_OFF + (uint32_t)(arow * EPH + acolh) * 2;
    const uint32_t koff0  = (uint32_t)((wn * 16 + (mi >> 1) * 8 + rr) * KPH + (mi & 1) * 8) * 2;
    const uint32_t voff0  = (uint32_t)(((mi & 1) * 8 + rr) * VPH + wn * 32 + (mi >> 1) * 8) * 2;

    for (int kt = 0; kt < NT; ++kt) {
        const int cur = kt & 1;
        const int k0  = kt * BN;

        __syncthreads();                    // prev PV done with buf^1 & Es
        if (kt + 1 < NT) {
            stage(cur ^ 1, kt + 1);
            asm volatile("cp.async.wait_group 1;");
        } else {
            asm volatile("cp.async.wait_group 0;");
        }
        __syncthreads();                    // tile kt visible

        const uint32_t kbase = sb + KS_OFF + cur * KS_BYTES + koff0;
        const uint32_t vbase = sb + VS_OFF + cur * VS_BYTES + voff0;

        // ---- S = Q K'^T : warp tile 32(m) x 16(n), k=128 in 8 k16 steps ----
        float sacc[2][2][4];
        #pragma unroll
        for (int i = 0; i < 2; i++)
            #pragma unroll
            for (int j = 0; j < 2; j++)
                #pragma unroll
                for (int r = 0; r < 4; r++) sacc[i][j][r] = 0.0f;

        #pragma unroll
        for (int ks = 0; ks < 8; ++ks) {
            uint32_t a0[4], a1[4], bb[4];
            ldsm_x4(a0, qaddr0 + (uint32_t)(ks * 16) * 2);
            ldsm_x4(a1, qaddr0 + (uint32_t)(16 * QPH + ks * 16) * 2);
            ldsm_x4(bb, kbase + (uint32_t)(ks * 16) * 2);
            mma_f16(sacc[0][0][0], sacc[0][0][1], sacc[0][0][2], sacc[0][0][3],
                    a0[0], a0[1], a0[2], a0[3], bb[0], bb[1]);
            mma_f16(sacc[0][1][0], sacc[0][1][1], sacc[0][1][2], sacc[0][1][3],
                    a0[0], a0[1], a0[2], a0[3], bb[2], bb[3]);
            mma_f16(sacc[1][0][0], sacc[1][0][1], sacc[1][0][2], sacc[1][0][3],
                    a1[0], a1[1], a1[2], a1[3], bb[0], bb[1]);
            mma_f16(sacc[1][1][0], sacc[1][1][1], sacc[1][1][2], sacc[1][1][3],
                    a1[0], a1[1], a1[2], a1[3], bb[2], bb[3]);
        }

        // ---- epilogue: E = exp(S); attn gmem (fp32) + Es smem (fp16) ----
        #pragma unroll
        for (int i = 0; i < 2; i++) {
            const int rlo = wm * 32 + i * 16 + g;
            const int rhi = rlo + 8;
            #pragma unroll
            for (int j = 0; j < 2; j++) {
                const int cl = wn * 16 + j * 8 + 2 * t;
                float e0 = __expf(sacc[i][j][0]);
                float e1 = __expf(sacc[i][j][1]);
                float e2 = __expf(sacc[i][j][2]);
                float e3 = __expf(sacc[i][j][3]);
                lsum[i][0] += e0 + e1;
                lsum[i][1] += e2 + e3;
                *(float2*)(attn + (size_t)(brow + rlo) * NK_ + k0 + cl) = make_float2(e0, e1);
                *(float2*)(attn + (size_t)(brow + rhi) * NK_ + k0 + cl) = make_float2(e2, e3);
                __half2 hlo = __floats2half2_rn(e0, e1);
                __half2 hhi = __floats2half2_rn(e2, e3);
                Esw[(rlo * EPH + cl) >> 1] = *(uint32_t*)&hlo;
                Esw[(rhi * EPH + cl) >> 1] = *(uint32_t*)&hhi;
            }
        }
        __syncthreads();                    // Es visible

        // ---- O += E V : warp tile 32(m) x 32(n), k=64 in 4 k16 steps ----
        #pragma unroll
        for (int ks = 0; ks < 4; ++ks) {
            uint32_t a0[4], a1[4];
            ldsm_x4(a0, eaddr0 + (uint32_t)(ks * 16) * 2);
            ldsm_x4(a1, eaddr0 + (uint32_t)(16 * EPH + ks * 16) * 2);
            #pragma unroll
            for (int jp = 0; jp < 2; jp++) {
                uint32_t bb[4];
                ldsm_x4_trans(bb, vbase + (uint32_t)(ks * 16 * VPH + jp * 16) * 2);
                mma_f16(oacc[0][jp*2+0][0], oacc[0][jp*2+0][1], oacc[0][jp*2+0][2], oacc[0][jp*2+0][3],
                        a0[0], a0[1], a0[2], a0[3], bb[0], bb[1]);
                mma_f16(oacc[0][jp*2+1][0], oacc[0][jp*2+1][1], oacc[0][jp*2+1][2], oacc[0][jp*2+1][3],
                        a0[0], a0[1], a0[2], a0[3], bb[2], bb[3]);
                mma_f16(oacc[1][jp*2+0][0], oacc[1][jp*2+0][1], oacc[1][jp*2+0][2], oacc[1][jp*2+0][3],
                        a1[0], a1[1], a1[2], a1[3], bb[0], bb[1]);
                mma_f16(oacc[1][jp*2+1][0], oacc[1][jp*2+1][1], oacc[1][jp*2+1][2], oacc[1][jp*2+1][3],
                        a1[0], a1[1], a1[2], a1[3], bb[2], bb[3]);
            }
        }
    }

    // ---- reduce lsum (4 lanes/group, then across the 4 n-warps) ----
    #pragma unroll
    for (int i = 0; i < 2; i++)
        #pragma unroll
        for (int h = 0; h < 2; h++) {
            float s = lsum[i][h];
            s += __shfl_xor_sync(0xffffffffu, s, 1);
            s += __shfl_xor_sync(0xffffffffu, s, 2);
            if (t == 0) lsm[wn * BM + wm * 32 + i * 16 + h * 8 + g] = s;
        }
    __syncthreads();
    if (tid < BM) {
        float inv = 1.0f / (lsm[tid] + lsm[BM + tid] + lsm[2*BM + tid] + lsm[3*BM + tid]);
        lsm[tid] = inv;   // reuse row 0 as inv table
    }
    __syncthreads();

    // ---- write normalized O ----
    #pragma unroll
    for (int i = 0; i < 2; i++) {
        const int rlo = wm * 32 + i * 16 + g;
        const int rhi = rlo + 8;
        const float invlo = lsm[rlo];
        const float invhi = lsm[rhi];
        #pragma unroll
        for (int j = 0; j < 4; j++) {
            const int col = wn * 32 + j * 8 + 2 * t;
            *(float2*)(out + (size_t)(brow + rlo) * D_ + col) =
                make_float2(oacc[i][j][0] * invlo, oacc[i][j][1] * invlo);
            *(float2*)(out + (size_t)(brow + rhi) * D_ + col) =
                make_float2(oacc[i][j][2] * invhi, oacc[i][j][3] * invhi);
        }
    }

    // ---- fused attn rescale: this CTA's 128x2048 slab, in place ----
    // (attn writes above are CTA-local; __syncthreads makes them visible)
    float4* slab = (float4*)(attn + (size_t)brow * NK_);
    #pragma unroll 4
    for (int it = 0; it < BM; ++it) {
        float inv = lsm[it];
        float4 v = slab[it * (NK_/4) + tid];
        v.x *= inv; v.y *= inv; v.z *= inv; v.w *= inv;
        slab[it * (NK_/4) + tid] = v;
    }
}

// ---------------------------------------------------------------------------
extern "C" void kernel_launch(void* const* d_in, const int* in_sizes, int n_in,
                              void* d_out, int out_size) {
    const float* Q      = (const float*)d_in[0];
    const float* K      = (const float*)d_in[1];
    const float* V      = (const float*)d_in[2];
    const float* phases = (const float*)d_in[3];

    float* out  = (float*)d_out;
    float* attn = out + (size_t)B_ * NQ_ * D_;   // outputs: (output, attention)

    (void)in_sizes; (void)n_in; (void)out_size;

    cudaFuncSetAttribute(attn_kernel,
                         cudaFuncAttributeMaxDynamicSharedMemorySize, SMEM_BYTES);

    gate_kernel<<<(NK_ + 255) / 256, 256>>>(phases);
    convK_kernel<<<(B_ * NK_ * D_ / 4) / 256, 256>>>(K);
    convV_kernel<<<(B_ * NK_ * D_ / 4) / 256, 256>>>(V);

    dim3 grid(NQ_ / BM, B_);
    attn_kernel<<<grid, NTHREADS, SMEM_BYTES>>>(Q, out, attn);
}

// round 14
// speedup vs baseline: 1.1605x; 1.1605x over previous
#include <cuda_runtime.h>
#include <cuda_fp16.h>
#include <math.h>
#include <stdint.h>

// Problem constants (fixed by the reference)
#define B_   16
#define NQ_  2048
#define NK_  2048
#define D_   128

// Tiling
#define BM       128     // queries per block
#define BN       64      // keys per tile
#define NT       32      // NK_/BN tiles
#define NTHREADS 256     // 8 warps, each owns an m16 query slab

// smem pitches in halves — word-pitch ≡ 4 (mod 32) -> conflict-free ldmatrix
#define QPH 136
#define KPH 136
#define VPH 136

// attn kernel smem layout
#define QS_OFF   0
#define QS_BYTES (BM * QPH * 2)                 // 34816
#define KS_OFF   (QS_OFF + QS_BYTES)
#define KS_BYTES (BN * KPH * 2)                 // 17408 per buffer
#define VS_OFF   (KS_OFF + 2 * KS_BYTES)
#define VS_BYTES (BN * VPH * 2)                 // 17408 per buffer
#define SMEM_BYTES (VS_OFF + 2 * VS_BYTES)      // 104448

// lsum kernel smem: Q + 2 K buffers
#define LSM_BYTES (QS_BYTES + 2 * KS_BYTES)     // 69632

__device__ float  g_gate[NK_];                     // gate * 1/sqrt(d)
__device__ float  g_inv_l[B_ * NQ_];
__device__ __half g_Kh[(size_t)B_ * NK_ * D_];     // K * gate * scale, fp16
__device__ __half g_Vh[(size_t)B_ * NK_ * D_];     // V, fp16 (row-major [key][d])

// ---------------------------------------------------------------------------
__global__ void gate_kernel(const float* __restrict__ phases) {
    int k = blockIdx.x * blockDim.x + threadIdx.x;
    if (k < NK_) {
        const float TWO_PI = 6.283185307179586f;
        const float INV_2PW2 = 1.0f / 1.2337005501361697f; // 2*(2pi/8)^2
        const float SCALE = 0.08838834764831845f;          // 1/sqrt(128)
        float p = fabsf(phases[k]);
        float pd = fminf(p, TWO_PI - p);
        g_gate[k] = expf(-pd * pd * INV_2PW2) * SCALE;
    }
}

__global__ void convK_kernel(const float* __restrict__ K) {
    int i = blockIdx.x * blockDim.x + threadIdx.x;   // < B*NK*D/4 = 2^20
    int d4  = (i & 31) << 2;
    int row = i >> 5;
    float gs = g_gate[row & (NK_ - 1)];
    float4 v = *(const float4*)(K + (size_t)row * D_ + d4);
    __half2 h0 = __floats2half2_rn(v.x * gs, v.y * gs);
    __half2 h1 = __floats2half2_rn(v.z * gs, v.w * gs);
    uint2 u = make_uint2(*(uint32_t*)&h0, *(uint32_t*)&h1);
    *(uint2*)&g_Kh[(size_t)row * D_ + d4] = u;
}

__global__ void convV_kernel(const float* __restrict__ V) {
    int i = blockIdx.x * blockDim.x + threadIdx.x;   // < 2^20
    int d4  = (i & 31) << 2;
    int row = i >> 5;
    float4 v = *(const float4*)(V + (size_t)row * D_ + d4);
    __half2 h0 = __floats2half2_rn(v.x, v.y);
    __half2 h1 = __floats2half2_rn(v.z, v.w);
    uint2 u = make_uint2(*(uint32_t*)&h0, *(uint32_t*)&h1);
    *(uint2*)&g_Vh[(size_t)row * D_ + d4] = u;
}

// ---------------------------------------------------------------------------
__device__ __forceinline__ void mma_f16(
    float& d0, float& d1, float& d2, float& d3,
    uint32_t a0, uint32_t a1, uint32_t a2, uint32_t a3,
    uint32_t b0, uint32_t b1)
{
    asm volatile(
        "mma.sync.aligned.m16n8k16.row.col.f32.f16.f16.f32 "
        "{%0,%1,%2,%3}, {%4,%5,%6,%7}, {%8,%9}, {%0,%1,%2,%3};"
        : "+f"(d0), "+f"(d1), "+f"(d2), "+f"(d3)
        : "r"(a0), "r"(a1), "r"(a2), "r"(a3), "r"(b0), "r"(b1));
}

__device__ __forceinline__ void ldsm_x4(uint32_t* r, uint32_t addr) {
    asm volatile("ldmatrix.sync.aligned.m8n8.x4.shared.b16 {%0,%1,%2,%3}, [%4];"
                 : "=r"(r[0]), "=r"(r[1]), "=r"(r[2]), "=r"(r[3]) : "r"(addr));
}

__device__ __forceinline__ void ldsm_x4_trans(uint32_t* r, uint32_t addr) {
    asm volatile("ldmatrix.sync.aligned.m8n8.x4.trans.shared.b16 {%0,%1,%2,%3}, [%4];"
                 : "=r"(r[0]), "=r"(r[1]), "=r"(r[2]), "=r"(r[3]) : "r"(addr));
}

__device__ __forceinline__ void cp16(uint32_t dst, const void* src) {
    asm volatile("cp.async.ca.shared.global [%0], [%1], 16;"
                 :: "r"(dst), "l"(src));
}

// ---------------------------------------------------------------------------
// Pass 1: l[b,q] = sum_k exp(q . k'), k' = K*gate*scale. Writes g_inv_l.
// 8 warps, warp = m16 slab, full n64 per tile. Q fragments hoisted in regs.
// ---------------------------------------------------------------------------
extern __shared__ char smem[];

__global__ void __launch_bounds__(NTHREADS, 2)
lsum_kernel(const float* __restrict__ Q)
{
    uint32_t sb = (uint32_t)__cvta_generic_to_shared(smem);
    uint32_t* Qsw = (uint32_t*)(smem + QS_OFF);

    const int b    = blockIdx.y;
    const int brow = b * NQ_ + blockIdx.x * BM;

    const int tid  = threadIdx.x;
    const int lane = tid & 31;
    const int wm   = tid >> 5;         // 0..7 -> m16 slab
    const int g    = lane >> 2;
    const int t    = lane & 3;
    const int mi   = lane >> 3;
    const int rr   = lane & 7;

    // stage Q fp32 -> fp16 smem
    const float* Qg = Q + (size_t)brow * D_;
    for (int i = tid; i < BM * (D_ / 4); i += NTHREADS) {
        int m  = i >> 5;
        int d4 = (i & 31) << 2;
        float4 v = *(const float4*)(Qg + m * D_ + d4);
        __half2 h0 = __floats2half2_rn(v.x, v.y);
        __half2 h1 = __floats2half2_rn(v.z, v.w);
        uint2 u = make_uint2(*(uint32_t*)&h0, *(uint32_t*)&h1);
        *(uint2*)&Qsw[(m * QPH + d4) >> 1] = u;
    }

    const __half* KhB = g_Kh + (size_t)b * NK_ * D_;
    auto stageK = [&](int buf, int kt) {
        uint32_t kdst = sb + KS_OFF + buf * KS_BYTES;
        const __half* ksrc = KhB + (size_t)(kt * BN) * D_;
        #pragma unroll
        for (int r = 0; r < 4; r++) {
            int i = tid + r * NTHREADS;          // < 1024
            int row = i >> 4, off = i & 15;
            cp16(kdst + row * (KPH * 2) + off * 16, ksrc + row * D_ + off * 8);
        }
        asm volatile("cp.async.commit_group;");
    };
    stageK(0, 0);
    __syncthreads();                             // Q visible

    // hoist Q fragments: m16 x k128 = 8 ldsm_x4
    const uint32_t qaddr0 = sb + QS_OFF +
        (uint32_t)((wm * 16 + rr + (mi & 1) * 8) * QPH + (mi >> 1) * 8) * 2;
    uint32_t qf[8][4];
    #pragma unroll
    for (int ks = 0; ks < 8; ++ks) ldsm_x4(qf[ks], qaddr0 + (uint32_t)(ks * 16) * 2);

    const uint32_t koff0 = (uint32_t)(((mi >> 1) * 8 + rr) * KPH + (mi & 1) * 8) * 2;
    float ls0 = 0.0f, ls1 = 0.0f;

    for (int kt = 0; kt < NT; ++kt) {
        const int cur = kt & 1;
        __syncthreads();
        if (kt + 1 < NT) { stageK(cur ^ 1, kt + 1); asm volatile("cp.async.wait_group 1;"); }
        else             { asm volatile("cp.async.wait_group 0;"); }
        __syncthreads();

        const uint32_t kbase = sb + KS_OFF + cur * KS_BYTES + koff0;

        float sacc[8][4];
        #pragma unroll
        for (int j = 0; j < 8; j++)
            #pragma unroll
            for (int r = 0; r < 4; r++) sacc[j][r] = 0.0f;

        #pragma unroll
        for (int ks = 0; ks < 8; ++ks) {
            #pragma unroll
            for (int jn = 0; jn < 4; ++jn) {
                uint32_t bb[4];
                ldsm_x4(bb, kbase + (uint32_t)(jn * 16 * KPH + ks * 16) * 2);
                mma_f16(sacc[2*jn][0], sacc[2*jn][1], sacc[2*jn][2], sacc[2*jn][3],
                        qf[ks][0], qf[ks][1], qf[ks][2], qf[ks][3], bb[0], bb[1]);
                mma_f16(sacc[2*jn+1][0], sacc[2*jn+1][1], sacc[2*jn+1][2], sacc[2*jn+1][3],
                        qf[ks][0], qf[ks][1], qf[ks][2], qf[ks][3], bb[2], bb[3]);
            }
        }
        #pragma unroll
        for (int j = 0; j < 8; j++) {
            ls0 += __expf(sacc[j][0]) + __expf(sacc[j][1]);
            ls1 += __expf(sacc[j][2]) + __expf(sacc[j][3]);
        }
    }

    // reduce across the 4 t-lanes of each group
    ls0 += __shfl_xor_sync(0xffffffffu, ls0, 1);
    ls0 += __shfl_xor_sync(0xffffffffu, ls0, 2);
    ls1 += __shfl_xor_sync(0xffffffffu, ls1, 1);
    ls1 += __shfl_xor_sync(0xffffffffu, ls1, 2);
    if (t == 0) {
        g_inv_l[brow + wm * 16 + g]     = 1.0f / ls0;
        g_inv_l[brow + wm * 16 + 8 + g] = 1.0f / ls1;
    }
}

// ---------------------------------------------------------------------------
// Pass 2: with inv_l known, write NORMALIZED attention directly and compute O.
// FA2 register passing: exp'd S fragments convert in-register to PV A
// fragments (no Es smem, no extra sync). Warp = m16 slab x full n64/k64.
// ---------------------------------------------------------------------------
__global__ void __launch_bounds__(NTHREADS, 1)
attn_kernel(const float* __restrict__ Q, float* __restrict__ out,
            float* __restrict__ attn)
{
    uint32_t sb = (uint32_t)__cvta_generic_to_shared(smem);
    uint32_t* Qsw = (uint32_t*)(smem + QS_OFF);

    const int b    = blockIdx.y;
    const int brow = b * NQ_ + blockIdx.x * BM;

    const int tid  = threadIdx.x;
    const int lane = tid & 31;
    const int wm   = tid >> 5;         // 0..7 -> m16 slab
    const int g    = lane >> 2;
    const int t    = lane & 3;
    const int mi   = lane >> 3;
    const int rr   = lane & 7;

    const float inv0 = g_inv_l[brow + wm * 16 + g];
    const float inv1 = g_inv_l[brow + wm * 16 + 8 + g];

    // stage Q fp32 -> fp16 smem
    const float* Qg = Q + (size_t)brow * D_;
    for (int i = tid; i < BM * (D_ / 4); i += NTHREADS) {
        int m  = i >> 5;
        int d4 = (i & 31) << 2;
        float4 v = *(const float4*)(Qg + m * D_ + d4);
        __half2 h0 = __floats2half2_rn(v.x, v.y);
        __half2 h1 = __floats2half2_rn(v.z, v.w);
        uint2 u = make_uint2(*(uint32_t*)&h0, *(uint32_t*)&h1);
        *(uint2*)&Qsw[(m * QPH + d4) >> 1] = u;
    }

    const __half* KhB = g_Kh + (size_t)b * NK_ * D_;
    const __half* VhB = g_Vh + (size_t)b * NK_ * D_;
    auto stageKV = [&](int buf, int kt) {
        const int k0 = kt * BN;
        uint32_t kdst = sb + KS_OFF + buf * KS_BYTES;
        uint32_t vdst = sb + VS_OFF + buf * VS_BYTES;
        const __half* ksrc = KhB + (size_t)k0 * D_;
        const __half* vsrc = VhB + (size_t)k0 * D_;
        #pragma unroll
        for (int r = 0; r < 4; r++) {
            int i = tid + r * NTHREADS;          // < 1024
            int row = i >> 4, off = i & 15;
            cp16(kdst + row * (KPH * 2) + off * 16, ksrc + row * D_ + off * 8);
            cp16(vdst + row * (VPH * 2) + off * 16, vsrc + row * D_ + off * 8);
        }
        asm volatile("cp.async.commit_group;");
    };
    stageKV(0, 0);
    __syncthreads();                             // Q visible

    // hoist Q fragments: m16 x k128
    const uint32_t qaddr0 = sb + QS_OFF +
        (uint32_t)((wm * 16 + rr + (mi & 1) * 8) * QPH + (mi >> 1) * 8) * 2;
    uint32_t qf[8][4];
    #pragma unroll
    for (int ks = 0; ks < 8; ++ks) ldsm_x4(qf[ks], qaddr0 + (uint32_t)(ks * 16) * 2);

    const uint32_t koff0 = (uint32_t)(((mi >> 1) * 8 + rr) * KPH + (mi & 1) * 8) * 2;
    const uint32_t voff0 = (uint32_t)((((mi & 1) * 8 + rr)) * VPH + (mi >> 1) * 8) * 2;

    float oacc[16][4];
    #pragma unroll
    for (int j = 0; j < 16; j++)
        #pragma unroll
        for (int r = 0; r < 4; r++) oacc[j][r] = 0.0f;

    float* arow0 = attn + (size_t)(brow + wm * 16 + g) * NK_;
    float* arow1 = attn + (size_t)(brow + wm * 16 + 8 + g) * NK_;

    for (int kt = 0; kt < NT; ++kt) {
        const int cur = kt & 1;
        const int k0  = kt * BN;

        __syncthreads();                 // all warps done with buf cur^1
        if (kt + 1 < NT) { stageKV(cur ^ 1, kt + 1); asm volatile("cp.async.wait_group 1;"); }
        else             { asm volatile("cp.async.wait_group 0;"); }
        __syncthreads();                 // tile kt visible

        const uint32_t kbase = sb + KS_OFF + cur * KS_BYTES + koff0;
        const uint32_t vbase = sb + VS_OFF + cur * VS_BYTES + voff0;

        // ---- S = Q K'^T : m16 x n64, k=128 ----
        float sacc[8][4];
        #pragma unroll
        for (int j = 0; j < 8; j++)
            #pragma unroll
            for (int r = 0; r < 4; r++) sacc[j][r] = 0.0f;

        #pragma unroll
        for (int ks = 0; ks < 8; ++ks) {
            #pragma unroll
            for (int jn = 0; jn < 4; ++jn) {
                uint32_t bb[4];
                ldsm_x4(bb, kbase + (uint32_t)(jn * 16 * KPH + ks * 16) * 2);
                mma_f16(sacc[2*jn][0], sacc[2*jn][1], sacc[2*jn][2], sacc[2*jn][3],
                        qf[ks][0], qf[ks][1], qf[ks][2], qf[ks][3], bb[0], bb[1]);
                mma_f16(sacc[2*jn+1][0], sacc[2*jn+1][1], sacc[2*jn+1][2], sacc[2*jn+1][3],
                        qf[ks][0], qf[ks][1], qf[ks][2], qf[ks][3], bb[2], bb[3]);
            }
        }

        // ---- epilogue: E = exp(S); write NORMALIZED attn; build PV A frags ----
        uint32_t ah[8][2];
        #pragma unroll
        for (int j = 0; j < 8; j++) {
            float e0 = __expf(sacc[j][0]);
            float e1 = __expf(sacc[j][1]);
            float e2 = __expf(sacc[j][2]);
            float e3 = __expf(sacc[j][3]);
            __half2 h0 = __floats2half2_rn(e0, e1);
            __half2 h1 = __floats2half2_rn(e2, e3);
            ah[j][0] = *(uint32_t*)&h0;
            ah[j][1] = *(uint32_t*)&h1;
            const int c = k0 + j * 8 + 2 * t;
            *(float2*)(arow0 + c) = make_float2(e0 * inv0, e1 * inv0);
            *(float2*)(arow1 + c) = make_float2(e2 * inv1, e3 * inv1);
        }

        // ---- O += E V : m16 x d128, k=64 (A from registers, B via ldsm.trans) ----
        #pragma unroll
        for (int ks = 0; ks < 4; ++ks) {
            const uint32_t a0 = ah[2*ks][0],   a1 = ah[2*ks][1];
            const uint32_t a2 = ah[2*ks+1][0], a3 = ah[2*ks+1][1];
            #pragma unroll
            for (int j16 = 0; j16 < 8; ++j16) {
                uint32_t bb[4];
                ldsm_x4_trans(bb, vbase + (uint32_t)(ks * 16 * VPH + j16 * 16) * 2);
                mma_f16(oacc[2*j16][0], oacc[2*j16][1], oacc[2*j16][2], oacc[2*j16][3],
                        a0, a1, a2, a3, bb[0], bb[1]);
                mma_f16(oacc[2*j16+1][0], oacc[2*j16+1][1], oacc[2*j16+1][2], oacc[2*j16+1][3],
                        a0, a1, a2, a3, bb[2], bb[3]);
            }
        }
    }

    // ---- write normalized O ----
    float* orow0 = out + (size_t)(brow + wm * 16 + g) * D_;
    float* orow1 = out + (size_t)(brow + wm * 16 + 8 + g) * D_;
    #pragma unroll
    for (int j = 0; j < 16; j++) {
        const int c = j * 8 + 2 * t;
        *(float2*)(orow0 + c) = make_float2(oacc[j][0] * inv0, oacc[j][1] * inv0);
        *(float2*)(orow1 + c) = make_float2(oacc[j][2] * inv1, oacc[j][3] * inv1);
    }
}

// ---------------------------------------------------------------------------
extern "C" void kernel_launch(void* const* d_in, const int* in_sizes, int n_in,
                              void* d_out, int out_size) {
    const float* Q      = (const float*)d_in[0];
    const float* K      = (const float*)d_in[1];
    const float* V      = (const float*)d_in[2];
    const float* phases = (const float*)d_in[3];

    float* out  = (float*)d_out;
    float* attn = out + (size_t)B_ * NQ_ * D_;   // outputs: (output, attention)

    (void)in_sizes; (void)n_in; (void)out_size;

    cudaFuncSetAttribute(lsum_kernel,
                         cudaFuncAttributeMaxDynamicSharedMemorySize, LSM_BYTES);
    cudaFuncSetAttribute(attn_kernel,
                         cudaFuncAttributeMaxDynamicSharedMemorySize, SMEM_BYTES);

    gate_kernel<<<(NK_ + 255) / 256, 256>>>(phases);
    convK_kernel<<<(B_ * NK_ * D_ / 4) / 256, 256>>>(K);
    convV_kernel<<<(B_ * NK_ * D_ / 4) / 256, 256>>>(V);

    dim3 grid(NQ_ / BM, B_);
    lsum_kernel<<<grid, NTHREADS, LSM_BYTES>>>(Q);
    attn_kernel<<<grid, NTHREADS, SMEM_BYTES>>>(Q, out, attn);
}